// round 15
// baseline (speedup 1.0000x reference)
#include <cuda_runtime.h>
#include <math.h>

#define BS 8
#define CC 256
#define NN 1500
#define HH 8
#define DK 32
#define NPAD 1504
#define NGROUPS ((BS * NN + 7) / 8)

// ---------------- scratch (static device globals; no allocs) ----------------
// q/k/v stored head-interleaved: [b][n][h*DK]  (256 floats per token row)
__device__ float g_q[(size_t)BS * NN * CC];
__device__ float g_k[(size_t)BS * NN * CC];
__device__ float g_v[(size_t)BS * NN * CC];
__device__ float g_val[(size_t)BS * NN * CC];              // [b][n][c]
__device__ unsigned short g_nbr[(size_t)BS * NN * NN];     // per-row neighbor j lists
__device__ int g_cnt[BS * NN];
__device__ int g_perm[BS * NN];                            // spatial-sorted order
__device__ int g_ctr;                                      // work-steal counter

// ---------------- fused prep: sort (8) + mask (1504) + qkv (1152) -----------
#define SORT_BLKS 8
#define MASK_BLKS (188 * BS)
#define QKV_BLKS  (6 * BS * HH * 3)

__global__ __launch_bounds__(256, 5) void prep_kernel(const float* __restrict__ boxes,
                                                      const float* __restrict__ cm,
                                                      const float* __restrict__ qin,
                                                      const float* __restrict__ kin,
                                                      const float* __restrict__ vin,
                                                      const float* __restrict__ wq,
                                                      const float* __restrict__ wk,
                                                      const float* __restrict__ wv) {
    __shared__ __align__(16) char sbuf[NPAD * 24];   // 36096 B union
    int blk = blockIdx.x;
    int t = threadIdx.x;

    if (blk < SORT_BLKS) {
        // ----- spatial counting sort, one block per batch -----
        int* hist = (int*)sbuf;
        int* offs = hist + 64;
        int b = blk;
        if (t < 64) hist[t] = 0;
        __syncthreads();
        const float4* bb = (const float4*)(boxes + (size_t)b * NN * 4);
        for (int n = t; n < NN; n += 256) {
            float4 bx = bb[n];
            int kx = min(7, max(0, (int)(bx.x * 8.0f)));
            int ky = min(7, max(0, (int)(bx.y * 8.0f)));
            atomicAdd(&hist[kx * 8 + ky], 1);
        }
        __syncthreads();
        if (t == 0) {
            int run = 0;
            for (int k = 0; k < 64; k++) { offs[k] = run; run += hist[k]; }
        }
        __syncthreads();
        for (int n = t; n < NN; n += 256) {
            float4 bx = bb[n];
            int kx = min(7, max(0, (int)(bx.x * 8.0f)));
            int ky = min(7, max(0, (int)(bx.y * 8.0f)));
            int pos = atomicAdd(&offs[kx * 8 + ky], 1);
            g_perm[b * NN + pos] = n;
        }
        return;
    }

    if (blk < SORT_BLKS + MASK_BLKS) {
        // ----- mask + neighbor list, warp per query (padded, no bounds chk) --
        int u = blk - SORT_BLKS;
        int b = u / 188;
        int bx = u % 188;
        float4* sbox = (float4*)sbuf;                 // (x1, y1, x2, y2)
        float2* sac = (float2*)(sbuf + NPAD * 16);    // (area, cm)
        const float4* bb = (const float4*)(boxes + (size_t)b * NN * 4);
        for (int idx = t; idx < NPAD; idx += 256) {
            if (idx < NN) {
                float4 bxv = bb[idx];
                float x1 = bxv.x - 0.5f * bxv.z;
                float x2 = bxv.x + 0.5f * bxv.z;
                float y1 = bxv.y - 0.5f * bxv.w;
                float y2 = bxv.y + 0.5f * bxv.w;
                sbox[idx] = make_float4(x1, y1, x2, y2);
                sac[idx] = make_float2((x2 - x1) * (y2 - y1),
                                       cm[(size_t)b * NN + idx]);
            } else {
                sbox[idx] = make_float4(1e30f, 1e30f, -1e30f, -1e30f);
                sac[idx] = make_float2(1.0f, 1.0f);   // iw=0 -> never a neighbor
            }
        }
        __syncthreads();

        int warp = t >> 5, lane = t & 31;
        int i = bx * 8 + warp;
        if (i >= NN) return;
        float4 bi = sbox[i];
        float2 aci = sac[i];
        unsigned short* out = g_nbr + ((size_t)b * NN + i) * NN;
        int cnt = 0;
        for (int jb = 0; jb < NPAD; jb += 32) {
            int j = jb + lane;
            float4 bj = sbox[j];
            float2 acj = sac[j];
            float ltx = fmaxf(bi.x, bj.x);
            float lty = fmaxf(bi.y, bj.y);
            float rbx = fminf(bi.z, bj.z);
            float rby = fminf(bi.w, bj.w);
            float iw = fmaxf(rbx - ltx, 0.0f);
            float ih = fmaxf(rby - lty, 0.0f);
            float inter = iw * ih;
            float uni = (aci.x + acj.x) - inter;
            float prod = aci.y * acj.y;
            bool nbq;
            if (prod == 1.0f) {
                // exact predicate for fl_RN(inter/uni) > 0.5, no divide
                float i2 = inter + inter;
                if (i2 > uni * 1.00001f) nbq = true;
                else if (i2 < uni * 0.99999f) nbq = false;
                else nbq = ((double)inter >
                            (double)uni * 0.5000000298023223876953125);
            } else {
                float iou = __fdiv_rn(inter, uni);
                nbq = (iou * prod) > 0.5f;
            }
            unsigned bal = __ballot_sync(0xffffffffu, nbq);
            int pos = cnt + __popc(bal & ((1u << lane) - 1u));
            if (nbq) out[pos] = (unsigned short)j;
            cnt += __popc(bal);
        }
        if (lane == 0) g_cnt[b * NN + i] = cnt;
        return;
    }

    // ----- qkv head projections: 2x2 (dhalf x jhalf) register-lean tiles ----
    // x16[16]+outv[16] keeps the branch ~50 regs so the fused kernel fits 5
    // blocks/SM. Staged coalesced stores (8 lines/wavefront) as before.
    {
        int u = blk - SORT_BLKS - MASK_BLKS;       // [0, 1152)
        int mat = u / (6 * BS * HH);
        int r = u % (6 * BS * HH);
        int bh = r / 6;
        int xc = r % 6;
        int b = bh >> 3, h = bh & 7;
        int warp = t >> 5, lane = t & 31;
        float4* sw = (float4*)sbuf;                 // 32x32 weights (4KB)
        float* stage = (float*)(sbuf + 4096);       // [16][257] floats
        const float* W = (mat == 0 ? wq : (mat == 1 ? wk : wv)) + h * DK * DK;
        const float* X = (mat == 0 ? qin : (mat == 1 ? kin : vin));
        float* O = (mat == 0 ? g_q : (mat == 1 ? g_k : g_v));
        sw[t] = ((const float4*)W)[t];
        __syncthreads();

        int i = xc * 256 + t;
        bool valid = i < NN;
        const float* xp = X + ((size_t)b * CC + h * DK) * NN + i;
        int lg = lane >> 2, q = lane & 3;

#pragma unroll
        for (int dhalf = 0; dhalf < 2; dhalf++) {
            float outv[16];
#pragma unroll
            for (int d = 0; d < 16; d++) outv[d] = 0.0f;
#pragma unroll
            for (int jh = 0; jh < 2; jh++) {
                float x16[16];
#pragma unroll
                for (int j = 0; j < 16; j++)
                    x16[j] = valid ? xp[(size_t)(jh * 16 + j) * NN] : 0.0f;
#pragma unroll
                for (int d = 0; d < 16; d++) {
                    int de = dhalf * 16 + d;
                    float acc = outv[d];
#pragma unroll
                    for (int jq = 0; jq < 4; jq++) {
                        float4 w4 = sw[de * 8 + jh * 4 + jq];
                        acc = fmaf(w4.x, x16[jq * 4 + 0], acc);
                        acc = fmaf(w4.y, x16[jq * 4 + 1], acc);
                        acc = fmaf(w4.z, x16[jq * 4 + 2], acc);
                        acc = fmaf(w4.w, x16[jq * 4 + 3], acc);
                    }
                    outv[d] = acc;
                }
            }
            if (dhalf == 1) __syncthreads();   // prior stage reads complete
#pragma unroll
            for (int d = 0; d < 16; d++)
                stage[d * 257 + t] = outv[d];
            __syncthreads();

            // coalesced stores: warp w covers tokens [w*32, w*32+32), 8/iter
#pragma unroll
            for (int it = 0; it < 4; it++) {
                int n = warp * 32 + it * 8 + lg;
                int gi = xc * 256 + n;
                if (gi < NN) {
                    float f0 = stage[(q * 4 + 0) * 257 + n];
                    float f1 = stage[(q * 4 + 1) * 257 + n];
                    float f2 = stage[(q * 4 + 2) * 257 + n];
                    float f3 = stage[(q * 4 + 3) * 257 + n];
                    *(float4*)(O + ((size_t)b * NN + gi) * CC + h * DK
                               + dhalf * 16 + q * 4) = make_float4(f0, f1, f2, f3);
                }
            }
        }
    }
}

// ---------------- sparse masked attention (warp per query, ALL heads) -------
__device__ __forceinline__ void os_update(float& m, float& l, float4& o,
                                          float s, const float4& v) {
    float mn = fmaxf(m, s);
    float sc = __expf(m - mn);
    float p = __expf(s - mn);        // s==-inf (padding) -> p=0
    l = l * sc + p;
    o.x = fmaf(p, v.x, o.x * sc);
    o.y = fmaf(p, v.y, o.y * sc);
    o.z = fmaf(p, v.z, o.z * sc);
    o.w = fmaf(p, v.w, o.w * sc);
    m = mn;
}

__device__ void attn_one(int gs, int lane) {
    int b = gs / NN;
    int gi = b * NN + g_perm[gs];            // actual b*NN + i

    int cnt = g_cnt[gi];
    size_t rowq = (size_t)gi * CC;
    int lo = 4 * lane, hi = 128 + 4 * lane;
    const float* kbase = g_k + (size_t)b * NN * CC;
    const float* vbase = g_v + (size_t)b * NN * CC;
    float* valr = g_val + rowq;

    if (cnt == 0) {   // has_nb == 0 fallback: val = v
        const float* vr = g_v + rowq;
        *(float4*)(valr + lo) = *(const float4*)(vr + lo);
        *(float4*)(valr + hi) = *(const float4*)(vr + hi);
        return;
    }

    float4 q0 = *(const float4*)(g_q + rowq + lo);
    float4 q1 = *(const float4*)(g_q + rowq + hi);
    const unsigned short* nb = g_nbr + (size_t)gi * NN;
    int cm1 = cnt - 1;

    float minit = (cnt < NN) ? 0.0f : -INFINITY;
    float m0 = minit, m1 = minit, l0 = 0.f, l1 = 0.f;
    float4 o0 = {0,0,0,0}, o1 = {0,0,0,0};

#define R8(s) s += __shfl_xor_sync(0xffffffffu, s, 1); \
              s += __shfl_xor_sync(0xffffffffu, s, 2); \
              s += __shfl_xor_sync(0xffffffffu, s, 4);

    for (int t = 0; t < cnt; t += 2) {
        int jA = nb[t], jB = nb[min(t + 1, cm1)];
        const float* kA = kbase + (size_t)jA * CC;
        const float* vA = vbase + (size_t)jA * CC;
        const float* kB = kbase + (size_t)jB * CC;
        const float* vB = vbase + (size_t)jB * CC;
        float4 kA0 = *(const float4*)(kA + lo), kA1 = *(const float4*)(kA + hi);
        float4 vA0 = *(const float4*)(vA + lo), vA1 = *(const float4*)(vA + hi);
        float4 kB0 = *(const float4*)(kB + lo), kB1 = *(const float4*)(kB + hi);
        float4 vB0 = *(const float4*)(vB + lo), vB1 = *(const float4*)(vB + hi);

        float sA0 = q0.x * kA0.x + q0.y * kA0.y + q0.z * kA0.z + q0.w * kA0.w;
        float sA1 = q1.x * kA1.x + q1.y * kA1.y + q1.z * kA1.z + q1.w * kA1.w;
        float sB0 = q0.x * kB0.x + q0.y * kB0.y + q0.z * kB0.z + q0.w * kB0.w;
        float sB1 = q1.x * kB1.x + q1.y * kB1.y + q1.z * kB1.z + q1.w * kB1.w;
        R8(sA0) R8(sA1) R8(sB0) R8(sB1)
        if (t + 1 >= cnt) { sB0 = -INFINITY; sB1 = -INFINITY; }

        os_update(m0, l0, o0, sA0, vA0);
        os_update(m0, l0, o0, sB0, vB0);
        os_update(m1, l1, o1, sA1, vA1);
        os_update(m1, l1, o1, sB1, vB1);
    }
#undef R8

    float inv0 = 1.0f / (l0 + 1e-8f);
    float inv1 = 1.0f / (l1 + 1e-8f);
    *(float4*)(valr + lo) = make_float4(o0.x * inv0, o0.y * inv0,
                                        o0.z * inv0, o0.w * inv0);
    *(float4*)(valr + hi) = make_float4(o1.x * inv1, o1.y * inv1,
                                        o1.z * inv1, o1.w * inv1);
}

// Persistent work-stealing: 444 resident blocks pull 8-query groups off a
// global counter (reset via cudaMemsetAsync each launch). Output is per-query
// and order-independent -> deterministic.
__global__ __launch_bounds__(256, 3) void attn_kernel() {
    __shared__ int sgrp;
    int warp = threadIdx.x >> 5, lane = threadIdx.x & 31;
    for (;;) {
        __syncthreads();                 // protect sgrp from prior-iter reads
        if (threadIdx.x == 0) sgrp = atomicAdd(&g_ctr, 1);
        __syncthreads();
        int grp = sgrp;
        if (grp >= NGROUPS) return;      // uniform across block
        int gs = grp * 8 + warp;
        if (gs < BS * NN) attn_one(gs, lane);
    }
}

// ---------------- output projection  out = Wp @ val + b ---------------------
// Known-best scalar version (measured 48.4us): 128(co) x 64(i) tile, 128
// threads, 8x8 per thread, KC=32 with register-prefetch double buffering.
#define PCO 128
#define PII 64
#define PKC 32
__global__ __launch_bounds__(128) void proj_kernel(const float* __restrict__ wp,
                                                   const float* __restrict__ bp,
                                                   float* __restrict__ out) {
    __shared__ float Ws[PKC][PCO + 4];   // [ci][co]
    __shared__ float Vs[PKC][PII + 4];   // [ci][i]
    int b = blockIdx.z;
    int coT = blockIdx.y * PCO;
    int iT = blockIdx.x * PII;
    int t = threadIdx.x;
    int tx = t & 7;                    // i group: tx*4 and tx*4+32
    int ty = t >> 3;                   // co group (0..15): ty*4 and ty*4+64
    int ci4 = (t & 7) * 4;             // load column group (0..28)
    int r0 = t >> 3;                   // load row base (0..15)

    float4 wpre[8], vpre[4];
#pragma unroll
    for (int p = 0; p < 8; p++)
        wpre[p] = *(const float4*)&wp[(size_t)(coT + r0 + p * 16) * CC + ci4];
#pragma unroll
    for (int p = 0; p < 4; p++) {
        int gi = iT + r0 + p * 16;
        vpre[p] = (gi < NN) ? *(const float4*)&g_val[((size_t)b * NN + gi) * CC + ci4]
                            : make_float4(0.f, 0.f, 0.f, 0.f);
    }

    float acc[8][8] = {};

    for (int kc = 0; kc < CC; kc += PKC) {
#pragma unroll
        for (int p = 0; p < 8; p++) {
            int r = r0 + p * 16;
            Ws[ci4 + 0][r] = wpre[p].x; Ws[ci4 + 1][r] = wpre[p].y;
            Ws[ci4 + 2][r] = wpre[p].z; Ws[ci4 + 3][r] = wpre[p].w;
        }
#pragma unroll
        for (int p = 0; p < 4; p++) {
            int io = r0 + p * 16;
            Vs[ci4 + 0][io] = vpre[p].x; Vs[ci4 + 1][io] = vpre[p].y;
            Vs[ci4 + 2][io] = vpre[p].z; Vs[ci4 + 3][io] = vpre[p].w;
        }
        __syncthreads();

        if (kc + PKC < CC) {
            int kcn = kc + PKC;
#pragma unroll
            for (int p = 0; p < 8; p++)
                wpre[p] = *(const float4*)&wp[(size_t)(coT + r0 + p * 16) * CC + kcn + ci4];
#pragma unroll
            for (int p = 0; p < 4; p++) {
                int gi = iT + r0 + p * 16;
                vpre[p] = (gi < NN) ? *(const float4*)&g_val[((size_t)b * NN + gi) * CC + kcn + ci4]
                                    : make_float4(0.f, 0.f, 0.f, 0.f);
            }
        }

#pragma unroll 8
        for (int ci = 0; ci < PKC; ci++) {
            float4 w0 = *(const float4*)&Ws[ci][ty * 4];
            float4 w1 = *(const float4*)&Ws[ci][64 + ty * 4];
            float4 v0 = *(const float4*)&Vs[ci][tx * 4];
            float4 v1 = *(const float4*)&Vs[ci][32 + tx * 4];
            float wr[8] = {w0.x, w0.y, w0.z, w0.w, w1.x, w1.y, w1.z, w1.w};
            float vr[8] = {v0.x, v0.y, v0.z, v0.w, v1.x, v1.y, v1.z, v1.w};
#pragma unroll
            for (int a = 0; a < 8; a++)
#pragma unroll
                for (int e = 0; e < 8; e++)
                    acc[a][e] = fmaf(wr[a], vr[e], acc[a][e]);
        }
        __syncthreads();
    }

#pragma unroll
    for (int a = 0; a < 8; a++) {
        int co = coT + (a < 4 ? (ty * 4 + a) : (64 + ty * 4 + (a - 4)));
        float bias = bp[co];
#pragma unroll
        for (int half = 0; half < 2; half++) {
            int gi = iT + (half == 0 ? tx * 4 : 32 + tx * 4);
            int e0 = half * 4;
            if (gi < NN) {   // NN % 4 == 0, whole float4 valid
                float4 r = make_float4(acc[a][e0 + 0] + bias, acc[a][e0 + 1] + bias,
                                       acc[a][e0 + 2] + bias, acc[a][e0 + 3] + bias);
                *(float4*)&out[((size_t)b * CC + co) * NN + gi] = r;
            }
        }
    }
}

// ---------------- launch ----------------------------------------------------
extern "C" void kernel_launch(void* const* d_in, const int* in_sizes, int n_in,
                              void* d_out, int out_size) {
    const float* queries = (const float*)d_in[0];
    const float* keys    = (const float*)d_in[1];
    const float* values  = (const float*)d_in[2];
    const float* boxes   = (const float*)d_in[3];
    const float* curmask = (const float*)d_in[4];
    const float* wq      = (const float*)d_in[5];
    const float* wk      = (const float*)d_in[6];
    const float* wv      = (const float*)d_in[7];
    const float* w_proj  = (const float*)d_in[8];
    const float* b_proj  = (const float*)d_in[9];
    float* out = (float*)d_out;

    void* ctr_ptr = nullptr;
    cudaGetSymbolAddress(&ctr_ptr, g_ctr);
    cudaMemsetAsync(ctr_ptr, 0, sizeof(int));

    prep_kernel<<<SORT_BLKS + MASK_BLKS + QKV_BLKS, 256>>>(
        boxes, curmask, queries, keys, values, wq, wk, wv);
    attn_kernel<<<444, 256>>>();
    proj_kernel<<<dim3((NN + PII - 1) / PII, CC / PCO, BS), 128>>>(w_proj, b_proj, out);
}

// round 16
// speedup vs baseline: 1.0705x; 1.0705x over previous
#include <cuda_runtime.h>
#include <math.h>

#define BS 8
#define CC 256
#define NN 1500
#define HH 8
#define DK 32
#define NPAD 1504

// ---------------- scratch (static device globals; no allocs) ----------------
// q/k/v stored head-interleaved: [b][n][h*DK]  (256 floats per token row)
__device__ float g_q[(size_t)BS * NN * CC];
__device__ float g_k[(size_t)BS * NN * CC];
__device__ float g_v[(size_t)BS * NN * CC];
__device__ float g_val[(size_t)BS * NN * CC];              // [b][n][c]
__device__ unsigned short g_nbr[(size_t)BS * NN * NN];     // per-row neighbor j lists
__device__ int g_cnt[BS * NN];
__device__ int g_perm[BS * NN];                            // spatial-sorted order

// ---------------- fused prep: sort (8) + mask (1504) + qkv (1152) -----------
#define SORT_BLKS 8
#define MASK_BLKS (188 * BS)
#define QKV_BLKS  (6 * BS * HH * 3)

__global__ __launch_bounds__(256, 4) void prep_kernel(const float* __restrict__ boxes,
                                                      const float* __restrict__ cm,
                                                      const float* __restrict__ qin,
                                                      const float* __restrict__ kin,
                                                      const float* __restrict__ vin,
                                                      const float* __restrict__ wq,
                                                      const float* __restrict__ wk,
                                                      const float* __restrict__ wv) {
    __shared__ __align__(16) char sbuf[NPAD * 24];   // 36096 B union
    int blk = blockIdx.x;
    int t = threadIdx.x;

    if (blk < SORT_BLKS) {
        // ----- spatial counting sort, one block per batch -----
        int* hist = (int*)sbuf;
        int* offs = hist + 64;
        int b = blk;
        if (t < 64) hist[t] = 0;
        __syncthreads();
        const float4* bb = (const float4*)(boxes + (size_t)b * NN * 4);
        for (int n = t; n < NN; n += 256) {
            float4 bx = bb[n];
            int kx = min(7, max(0, (int)(bx.x * 8.0f)));
            int ky = min(7, max(0, (int)(bx.y * 8.0f)));
            atomicAdd(&hist[kx * 8 + ky], 1);
        }
        __syncthreads();
        if (t == 0) {
            int run = 0;
            for (int k = 0; k < 64; k++) { offs[k] = run; run += hist[k]; }
        }
        __syncthreads();
        for (int n = t; n < NN; n += 256) {
            float4 bx = bb[n];
            int kx = min(7, max(0, (int)(bx.x * 8.0f)));
            int ky = min(7, max(0, (int)(bx.y * 8.0f)));
            int pos = atomicAdd(&offs[kx * 8 + ky], 1);
            g_perm[b * NN + pos] = n;
        }
        return;
    }

    if (blk < SORT_BLKS + MASK_BLKS) {
        // ----- mask + neighbor list, warp per query (padded, no bounds chk) --
        int u = blk - SORT_BLKS;
        int b = u / 188;
        int bx = u % 188;
        float4* sbox = (float4*)sbuf;                 // (x1, y1, x2, y2)
        float2* sac = (float2*)(sbuf + NPAD * 16);    // (area, cm)
        const float4* bb = (const float4*)(boxes + (size_t)b * NN * 4);
        for (int idx = t; idx < NPAD; idx += 256) {
            if (idx < NN) {
                float4 bxv = bb[idx];
                float x1 = bxv.x - 0.5f * bxv.z;
                float x2 = bxv.x + 0.5f * bxv.z;
                float y1 = bxv.y - 0.5f * bxv.w;
                float y2 = bxv.y + 0.5f * bxv.w;
                sbox[idx] = make_float4(x1, y1, x2, y2);
                sac[idx] = make_float2((x2 - x1) * (y2 - y1),
                                       cm[(size_t)b * NN + idx]);
            } else {
                sbox[idx] = make_float4(1e30f, 1e30f, -1e30f, -1e30f);
                sac[idx] = make_float2(1.0f, 1.0f);   // iw=0 -> never a neighbor
            }
        }
        __syncthreads();

        int warp = t >> 5, lane = t & 31;
        int i = bx * 8 + warp;
        if (i >= NN) return;
        float4 bi = sbox[i];
        float2 aci = sac[i];
        unsigned short* out = g_nbr + ((size_t)b * NN + i) * NN;
        int cnt = 0;
        for (int jb = 0; jb < NPAD; jb += 32) {
            int j = jb + lane;
            float4 bj = sbox[j];
            float2 acj = sac[j];
            float ltx = fmaxf(bi.x, bj.x);
            float lty = fmaxf(bi.y, bj.y);
            float rbx = fminf(bi.z, bj.z);
            float rby = fminf(bi.w, bj.w);
            float iw = fmaxf(rbx - ltx, 0.0f);
            float ih = fmaxf(rby - lty, 0.0f);
            float inter = iw * ih;
            float uni = (aci.x + acj.x) - inter;
            float prod = aci.y * acj.y;
            bool nbq;
            if (prod == 1.0f) {
                // exact predicate for fl_RN(inter/uni) > 0.5, no divide
                float i2 = inter + inter;
                if (i2 > uni * 1.00001f) nbq = true;
                else if (i2 < uni * 0.99999f) nbq = false;
                else nbq = ((double)inter >
                            (double)uni * 0.5000000298023223876953125);
            } else {
                float iou = __fdiv_rn(inter, uni);
                nbq = (iou * prod) > 0.5f;
            }
            unsigned bal = __ballot_sync(0xffffffffu, nbq);
            int pos = cnt + __popc(bal & ((1u << lane) - 1u));
            if (nbq) out[pos] = (unsigned short)j;
            cnt += __popc(bal);
        }
        if (lane == 0) g_cnt[b * NN + i] = cnt;
        return;
    }

    // ----- qkv head projections: two 16-d halves, staged coalesced stores ---
    {
        int u = blk - SORT_BLKS - MASK_BLKS;       // [0, 1152)
        int mat = u / (6 * BS * HH);
        int r = u % (6 * BS * HH);
        int bh = r / 6;
        int xc = r % 6;
        int b = bh >> 3, h = bh & 7;
        int warp = t >> 5, lane = t & 31;
        float4* sw = (float4*)sbuf;                 // 32x32 weights (4KB)
        float* stage = (float*)(sbuf + 4096);       // [16][257] floats
        const float* W = (mat == 0 ? wq : (mat == 1 ? wk : wv)) + h * DK * DK;
        const float* X = (mat == 0 ? qin : (mat == 1 ? kin : vin));
        float* O = (mat == 0 ? g_q : (mat == 1 ? g_k : g_v));
        sw[t] = ((const float4*)W)[t];
        __syncthreads();

        int i = xc * 256 + t;
        bool valid = i < NN;
        float x[DK];
        const float* xp = X + ((size_t)b * CC + h * DK) * NN + i;
#pragma unroll
        for (int j = 0; j < DK; j++) x[j] = valid ? xp[(size_t)j * NN] : 0.0f;

        int lg = lane >> 2, q = lane & 3;
#pragma unroll
        for (int half = 0; half < 2; half++) {
            float outv[16];
#pragma unroll
            for (int d = 0; d < 16; d++) {
                int de = half * 16 + d;
                float acc = 0.0f;
#pragma unroll
                for (int jq = 0; jq < 8; jq++) {
                    float4 w4 = sw[de * 8 + jq];
                    acc = fmaf(w4.x, x[jq * 4 + 0], acc);
                    acc = fmaf(w4.y, x[jq * 4 + 1], acc);
                    acc = fmaf(w4.z, x[jq * 4 + 2], acc);
                    acc = fmaf(w4.w, x[jq * 4 + 3], acc);
                }
                outv[d] = acc;
            }
            if (half == 1) __syncthreads();   // prior stage reads complete
#pragma unroll
            for (int d = 0; d < 16; d++)
                stage[d * 257 + t] = outv[d];
            __syncthreads();

            // coalesced stores: warp w covers tokens [w*32, w*32+32), 8/iter
#pragma unroll
            for (int it = 0; it < 4; it++) {
                int n = warp * 32 + it * 8 + lg;
                int gi = xc * 256 + n;
                if (gi < NN) {
                    float f0 = stage[(q * 4 + 0) * 257 + n];
                    float f1 = stage[(q * 4 + 1) * 257 + n];
                    float f2 = stage[(q * 4 + 2) * 257 + n];
                    float f3 = stage[(q * 4 + 3) * 257 + n];
                    *(float4*)(O + ((size_t)b * NN + gi) * CC + h * DK
                               + half * 16 + q * 4) = make_float4(f0, f1, f2, f3);
                }
            }
        }
    }
}

// ---------------- sparse masked attention (warp per query, ALL heads) -------
// Register-peak restructure: K loads -> dots (K dies) -> V loads issued under
// the shfl-reduction chain -> updates. Peak live regs ~64 -> 4 blocks/SM.
__device__ __forceinline__ void os_update(float& m, float& l, float4& o,
                                          float s, const float4& v) {
    float mn = fmaxf(m, s);
    float sc = __expf(m - mn);
    float p = __expf(s - mn);        // s==-inf (padding) -> p=0
    l = l * sc + p;
    o.x = fmaf(p, v.x, o.x * sc);
    o.y = fmaf(p, v.y, o.y * sc);
    o.z = fmaf(p, v.z, o.z * sc);
    o.w = fmaf(p, v.w, o.w * sc);
    m = mn;
}

__global__ __launch_bounds__(256, 4) void attn_kernel() {
    int warp = threadIdx.x >> 5, lane = threadIdx.x & 31;
    int gs = blockIdx.x * 8 + warp;          // sorted rank within b*NN
    if (gs >= BS * NN) return;
    int b = gs / NN;
    int gi = b * NN + g_perm[gs];            // actual b*NN + i

    int cnt = g_cnt[gi];
    size_t rowq = (size_t)gi * CC;
    int lo = 4 * lane, hi = 128 + 4 * lane;
    const float* kbase = g_k + (size_t)b * NN * CC;
    const float* vbase = g_v + (size_t)b * NN * CC;
    float* valr = g_val + rowq;

    if (cnt == 0) {   // has_nb == 0 fallback: val = v
        const float* vr = g_v + rowq;
        *(float4*)(valr + lo) = *(const float4*)(vr + lo);
        *(float4*)(valr + hi) = *(const float4*)(vr + hi);
        return;
    }

    float4 q0 = *(const float4*)(g_q + rowq + lo);
    float4 q1 = *(const float4*)(g_q + rowq + hi);
    const unsigned short* nb = g_nbr + (size_t)gi * NN;
    int cm1 = cnt - 1;

    float minit = (cnt < NN) ? 0.0f : -INFINITY;
    float m0 = minit, m1 = minit, l0 = 0.f, l1 = 0.f;
    float4 o0 = {0,0,0,0}, o1 = {0,0,0,0};

#define R8(s) s += __shfl_xor_sync(0xffffffffu, s, 1); \
              s += __shfl_xor_sync(0xffffffffu, s, 2); \
              s += __shfl_xor_sync(0xffffffffu, s, 4);

    for (int t = 0; t < cnt; t += 2) {
        int jA = nb[t], jB = nb[min(t + 1, cm1)];
        const float* kA = kbase + (size_t)jA * CC;
        const float* kB = kbase + (size_t)jB * CC;
        // K loads + dots (K regs die right after)
        float4 kA0 = *(const float4*)(kA + lo), kA1 = *(const float4*)(kA + hi);
        float4 kB0 = *(const float4*)(kB + lo), kB1 = *(const float4*)(kB + hi);
        float sA0 = q0.x * kA0.x + q0.y * kA0.y + q0.z * kA0.z + q0.w * kA0.w;
        float sA1 = q1.x * kA1.x + q1.y * kA1.y + q1.z * kA1.z + q1.w * kA1.w;
        float sB0 = q0.x * kB0.x + q0.y * kB0.y + q0.z * kB0.z + q0.w * kB0.w;
        float sB1 = q1.x * kB1.x + q1.y * kB1.y + q1.z * kB1.z + q1.w * kB1.w;

        // V loads issue here; latency overlaps the shfl-reduction chain
        const float* vA = vbase + (size_t)jA * CC;
        const float* vB = vbase + (size_t)jB * CC;
        float4 vA0 = *(const float4*)(vA + lo), vA1 = *(const float4*)(vA + hi);
        float4 vB0 = *(const float4*)(vB + lo), vB1 = *(const float4*)(vB + hi);

        R8(sA0) R8(sA1) R8(sB0) R8(sB1)
        if (t + 1 >= cnt) { sB0 = -INFINITY; sB1 = -INFINITY; }

        os_update(m0, l0, o0, sA0, vA0);
        os_update(m0, l0, o0, sB0, vB0);
        os_update(m1, l1, o1, sA1, vA1);
        os_update(m1, l1, o1, sB1, vB1);
    }
#undef R8

    float inv0 = 1.0f / (l0 + 1e-8f);
    float inv1 = 1.0f / (l1 + 1e-8f);
    *(float4*)(valr + lo) = make_float4(o0.x * inv0, o0.y * inv0,
                                        o0.z * inv0, o0.w * inv0);
    *(float4*)(valr + hi) = make_float4(o1.x * inv1, o1.y * inv1,
                                        o1.z * inv1, o1.w * inv1);
}

// ---------------- output projection  out = Wp @ val + b ---------------------
// Known-best scalar version (measured 48.4us): 128(co) x 64(i) tile, 128
// threads, 8x8 per thread, KC=32 with register-prefetch double buffering.
#define PCO 128
#define PII 64
#define PKC 32
__global__ __launch_bounds__(128) void proj_kernel(const float* __restrict__ wp,
                                                   const float* __restrict__ bp,
                                                   float* __restrict__ out) {
    __shared__ float Ws[PKC][PCO + 4];   // [ci][co]
    __shared__ float Vs[PKC][PII + 4];   // [ci][i]
    int b = blockIdx.z;
    int coT = blockIdx.y * PCO;
    int iT = blockIdx.x * PII;
    int t = threadIdx.x;
    int tx = t & 7;                    // i group: tx*4 and tx*4+32
    int ty = t >> 3;                   // co group (0..15): ty*4 and ty*4+64
    int ci4 = (t & 7) * 4;             // load column group (0..28)
    int r0 = t >> 3;                   // load row base (0..15)

    float4 wpre[8], vpre[4];
#pragma unroll
    for (int p = 0; p < 8; p++)
        wpre[p] = *(const float4*)&wp[(size_t)(coT + r0 + p * 16) * CC + ci4];
#pragma unroll
    for (int p = 0; p < 4; p++) {
        int gi = iT + r0 + p * 16;
        vpre[p] = (gi < NN) ? *(const float4*)&g_val[((size_t)b * NN + gi) * CC + ci4]
                            : make_float4(0.f, 0.f, 0.f, 0.f);
    }

    float acc[8][8] = {};

    for (int kc = 0; kc < CC; kc += PKC) {
#pragma unroll
        for (int p = 0; p < 8; p++) {
            int r = r0 + p * 16;
            Ws[ci4 + 0][r] = wpre[p].x; Ws[ci4 + 1][r] = wpre[p].y;
            Ws[ci4 + 2][r] = wpre[p].z; Ws[ci4 + 3][r] = wpre[p].w;
        }
#pragma unroll
        for (int p = 0; p < 4; p++) {
            int io = r0 + p * 16;
            Vs[ci4 + 0][io] = vpre[p].x; Vs[ci4 + 1][io] = vpre[p].y;
            Vs[ci4 + 2][io] = vpre[p].z; Vs[ci4 + 3][io] = vpre[p].w;
        }
        __syncthreads();

        if (kc + PKC < CC) {
            int kcn = kc + PKC;
#pragma unroll
            for (int p = 0; p < 8; p++)
                wpre[p] = *(const float4*)&wp[(size_t)(coT + r0 + p * 16) * CC + kcn + ci4];
#pragma unroll
            for (int p = 0; p < 4; p++) {
                int gi = iT + r0 + p * 16;
                vpre[p] = (gi < NN) ? *(const float4*)&g_val[((size_t)b * NN + gi) * CC + kcn + ci4]
                                    : make_float4(0.f, 0.f, 0.f, 0.f);
            }
        }

#pragma unroll 8
        for (int ci = 0; ci < PKC; ci++) {
            float4 w0 = *(const float4*)&Ws[ci][ty * 4];
            float4 w1 = *(const float4*)&Ws[ci][64 + ty * 4];
            float4 v0 = *(const float4*)&Vs[ci][tx * 4];
            float4 v1 = *(const float4*)&Vs[ci][32 + tx * 4];
            float wr[8] = {w0.x, w0.y, w0.z, w0.w, w1.x, w1.y, w1.z, w1.w};
            float vr[8] = {v0.x, v0.y, v0.z, v0.w, v1.x, v1.y, v1.z, v1.w};
#pragma unroll
            for (int a = 0; a < 8; a++)
#pragma unroll
                for (int e = 0; e < 8; e++)
                    acc[a][e] = fmaf(wr[a], vr[e], acc[a][e]);
        }
        __syncthreads();
    }

#pragma unroll
    for (int a = 0; a < 8; a++) {
        int co = coT + (a < 4 ? (ty * 4 + a) : (64 + ty * 4 + (a - 4)));
        float bias = bp[co];
#pragma unroll
        for (int half = 0; half < 2; half++) {
            int gi = iT + (half == 0 ? tx * 4 : 32 + tx * 4);
            int e0 = half * 4;
            if (gi < NN) {   // NN % 4 == 0, whole float4 valid
                float4 r = make_float4(acc[a][e0 + 0] + bias, acc[a][e0 + 1] + bias,
                                       acc[a][e0 + 2] + bias, acc[a][e0 + 3] + bias);
                *(float4*)&out[((size_t)b * CC + co) * NN + gi] = r;
            }
        }
    }
}

// ---------------- launch ----------------------------------------------------
extern "C" void kernel_launch(void* const* d_in, const int* in_sizes, int n_in,
                              void* d_out, int out_size) {
    const float* queries = (const float*)d_in[0];
    const float* keys    = (const float*)d_in[1];
    const float* values  = (const float*)d_in[2];
    const float* boxes   = (const float*)d_in[3];
    const float* curmask = (const float*)d_in[4];
    const float* wq      = (const float*)d_in[5];
    const float* wk      = (const float*)d_in[6];
    const float* wv      = (const float*)d_in[7];
    const float* w_proj  = (const float*)d_in[8];
    const float* b_proj  = (const float*)d_in[9];
    float* out = (float*)d_out;

    prep_kernel<<<SORT_BLKS + MASK_BLKS + QKV_BLKS, 256>>>(
        boxes, curmask, queries, keys, values, wq, wk, wv);
    attn_kernel<<<dim3((BS * NN + 7) / 8), 256>>>();
    proj_kernel<<<dim3((NN + PII - 1) / PII, CC / PCO, BS), 128>>>(w_proj, b_proj, out);
}